// round 11
// baseline (speedup 1.0000x reference)
#include <cuda_runtime.h>
#include <math.h>

#define NNODES 20000
#define NEDGES 320000
#define NT 4
#define NR 8
#define NH 4
#define DK 64
#define DIM 256
#define RH (NR*NH)

#define XPITCH 65
// dynamic smem for GEMM kernels: Xs[128][65] + Ws[64][64]
#define SMEM_BYTES ((128*XPITCH + 64*64) * 4)

// ---------------- scratch (static device globals; no allocation) ----------------
__device__ float g_k[NNODES*DIM];
__device__ float g_q[NNODES*DIM];
__device__ float g_v[NNODES*DIM];
__device__ float g_agg[NNODES*DIM];
__device__ float g_At[RH*DK*DK];                    // transposed relation_att
__device__ float g_kA[(size_t)NR*NNODES*DIM];       // [R][N][H*64] = A_r,h @ k
__device__ float g_s[(size_t)NNODES*NR*DIM];        // [N][R][H*64] per-rel alpha-weighted v
__device__ float g_ex[NEDGES*NH];                   // scores, then exp values
__device__ unsigned int g_mkey[NNODES*NH];          // encoded float max keys
__device__ float g_denom[NNODES*NH];
__device__ int g_cnt[NNODES];
__device__ int g_rowptr[NNODES+1];
__device__ int g_cursor[NNODES];
__device__ int g_elist[NEDGES];
__device__ int g_tcnt[NT];
__device__ int g_toff[NT];
__device__ int g_tcur[NT];
__device__ int g_order[NNODES];

// ---------------- helpers ----------------
__device__ __forceinline__ unsigned fenc(float f) {
    unsigned u = __float_as_uint(f);
    return (u & 0x80000000u) ? ~u : (u | 0x80000000u);
}
__device__ __forceinline__ float fdec(unsigned k) {
    unsigned u = (k & 0x80000000u) ? (k & 0x7FFFFFFFu) : ~k;
    return __uint_as_float(u);
}

// ---- f32x2 packed math (sm_100+; ptxas never auto-generates FFMA2) ----
__device__ __forceinline__ unsigned long long pack2(float lo, float hi) {
    unsigned long long r;
    asm("mov.b64 %0, {%1, %2};" : "=l"(r) : "f"(lo), "f"(hi));
    return r;
}
__device__ __forceinline__ void ffma2(unsigned long long& d,
                                      unsigned long long a, unsigned long long b) {
    asm("fma.rn.f32x2 %0, %1, %2, %0;" : "+l"(d) : "l"(a), "l"(b));
}
__device__ __forceinline__ unsigned long long fmul2(unsigned long long a,
                                                    unsigned long long b) {
    unsigned long long r;
    asm("mul.rn.f32x2 %0, %1, %2;" : "=l"(r) : "l"(a), "l"(b));
    return r;
}
__device__ __forceinline__ float2 unpack2(unsigned long long v) {
    float2 f;
    asm("mov.b64 {%0, %1}, %2;" : "=f"(f.x), "=f"(f.y) : "l"(v));
    return f;
}

// 128x64 C-tile, 128 threads (4 warps), 8x8 microtile, K=64 step.
// Warp w owns rows [w*32, w*32+32). Lane l loads Xs[w*32+l][k] (pitch 65 ->
// banks (l+k) mod 32, conflict-free, ONE wavefront per k). The 8 per-thread
// a-operands come via __shfl_sync — no smem bank traffic. W read via 2
// dedup'd LDS.128. Crossbar wavefronts per k per warp: 3 (was ~10).
// FFMA2 order is k-ascending: bit-identical results to passing kernels.
__device__ __forceinline__ void mm8x8(const float* Xs, const float* Ws,
                                      unsigned long long acc2[8][4], int tid) {
    int lane = tid & 31;
    int tj = lane & 7;
    int srcBase = lane & 24;              // (lane>>3)*8
    const float* arow = Xs + (size_t)((tid >> 5)*32 + lane)*XPITCH;
#pragma unroll 4
    for (int k = 0; k < 64; k++) {
        float a_l = arow[k];
        const float* w = Ws + k*64 + tj*8;
        ulonglong2 wa = *(const ulonglong2*)w;
        ulonglong2 wb = *(const ulonglong2*)(w + 4);
#pragma unroll
        for (int u = 0; u < 8; u++) {
            float au = __shfl_sync(0xFFFFFFFFu, a_l, srcBase | u);
            unsigned long long ad = pack2(au, au);
            ffma2(acc2[u][0], ad, wa.x);
            ffma2(acc2[u][1], ad, wa.y);
            ffma2(acc2[u][2], ad, wb.x);
            ffma2(acc2[u][3], ad, wb.y);
        }
    }
}

__device__ __forceinline__ void zero_acc(unsigned long long acc2[8][4]) {
#pragma unroll
    for (int u = 0; u < 8; u++)
#pragma unroll
        for (int j = 0; j < 4; j++) acc2[u][j] = 0ULL;
}

__device__ __forceinline__ void store_row(float* cp, const unsigned long long* row) {
    float2 p0 = unpack2(row[0]), p1 = unpack2(row[1]);
    float2 p2 = unpack2(row[2]), p3 = unpack2(row[3]);
    *(float4*)cp       = make_float4(p0.x, p0.y, p1.x, p1.y);
    *(float4*)(cp + 4) = make_float4(p2.x, p2.y, p3.x, p3.y);
}

// ---------------- setup kernels ----------------
__global__ void zero_rest_kernel() {
    int i = blockIdx.x*blockDim.x + threadIdx.x;
    if (i < NNODES*NH) { g_mkey[i] = 0u; g_denom[i] = 0.f; }
    if (i < NNODES) g_cnt[i] = 0;
}

// self-contained type histogram + offsets + cursor reset (single block)
__global__ void combo_hist_kernel(const int* __restrict__ ntype) {
    __shared__ int scnt[NT];
    int tid = threadIdx.x;
    if (tid < NT) scnt[tid] = 0;
    __syncthreads();
    int c0 = 0, c1 = 0, c2 = 0, c3 = 0;
    for (int i = tid; i < NNODES; i += 1024) {
        int t = ntype[i];
        c0 += (t == 0); c1 += (t == 1); c2 += (t == 2); c3 += (t == 3);
    }
#pragma unroll
    for (int off = 16; off > 0; off >>= 1) {
        c0 += __shfl_xor_sync(0xFFFFFFFFu, c0, off);
        c1 += __shfl_xor_sync(0xFFFFFFFFu, c1, off);
        c2 += __shfl_xor_sync(0xFFFFFFFFu, c2, off);
        c3 += __shfl_xor_sync(0xFFFFFFFFu, c3, off);
    }
    if ((tid & 31) == 0) {
        atomicAdd(&scnt[0], c0); atomicAdd(&scnt[1], c1);
        atomicAdd(&scnt[2], c2); atomicAdd(&scnt[3], c3);
    }
    __syncthreads();
    if (tid == 0) {
        int off = 0;
        for (int t = 0; t < NT; t++) {
            g_tcnt[t] = scnt[t];
            g_toff[t] = off;
            g_tcur[t] = 0;
            off += scnt[t];
        }
    }
}

__global__ void nscatter_kernel(const int* __restrict__ ntype) {
    int n = blockIdx.x*blockDim.x + threadIdx.x;
    if (n < NNODES) {
        int t = ntype[n];
        int p = atomicAdd(&g_tcur[t], 1);
        g_order[g_toff[t] + p] = n;
    }
}

__global__ void trans_kernel(const float* __restrict__ rA) {
    int rh = blockIdx.x;        // 0..31
    int e = threadIdx.x;        // 0..63
    const float* src = rA + rh*DK*DK;
    float* dst = g_At + rh*DK*DK;
#pragma unroll
    for (int d = 0; d < DK; d++)
        dst[e*DK + d] = src[d*DK + e];   // At[e][d] = A[d][e]
}

// ---------------- GEMM kernels ----------------
// typed K/Q/V projection: grid (157, type, mat*4+coltile), block 128
__global__ __launch_bounds__(128) void kqv_kernel(
    const float* __restrict__ hin, const float* __restrict__ kW,
    const float* __restrict__ qW, const float* __restrict__ vW) {
    extern __shared__ float sm[];
    float* Xs = sm;                  // 128*XPITCH
    float* Ws = sm + 128*XPITCH;     // 64*64
    int t = blockIdx.y;
    int cnt = g_tcnt[t];
    int tile = blockIdx.x * 128;
    if (tile >= cnt) return;
    int base = g_toff[t];
    int mat = blockIdx.z >> 2;
    int c4  = blockIdx.z & 3;
    const float* W = (mat == 0 ? kW : (mat == 1 ? qW : vW)) + (size_t)t*DIM*DIM + c4*64;
    float* C = (mat == 0 ? g_k : (mat == 1 ? g_q : g_v));
    int tid = threadIdx.x;
    int ti = tid >> 3, tj = tid & 7;
    unsigned long long acc2[8][4];
    zero_acc(acc2);

    for (int kb = 0; kb < 4; kb++) {
        __syncthreads();
#pragma unroll
        for (int p = 0; p < 16; p++) {
            int lr = p*8 + (tid >> 4);
            int lc = (tid & 15)*4;
            float4 x4 = make_float4(0.f, 0.f, 0.f, 0.f);
            int gi = tile + lr;
            if (gi < cnt) {
                int node = g_order[base + gi];
                x4 = *(const float4*)(hin + (size_t)node*DIM + kb*64 + lc);
            }
            float* xp = Xs + lr*XPITCH + lc;
            xp[0] = x4.x; xp[1] = x4.y; xp[2] = x4.z; xp[3] = x4.w;
        }
#pragma unroll
        for (int i = 0; i < 8; i++) {
            int lin = tid*32 + i*4;
            int kk = lin >> 6, d = lin & 63;
            float4 w4 = *(const float4*)(W + (size_t)(kb*64 + kk)*DIM + d);
            *(float4*)(Ws + kk*64 + d) = w4;
        }
        __syncthreads();
        mm8x8(Xs, Ws, acc2, tid);
    }
#pragma unroll
    for (int u = 0; u < 8; u++) {
        int gi = tile + ti*8 + u;
        if (gi < cnt) {
            int node = g_order[base + gi];
            store_row(C + (size_t)node*DIM + c4*64 + tj*8, acc2[u]);
        }
    }
}

// kA[r,n,h,:] = A_{r,h} @ k[n,h,:]  : grid (157, 32), block 128
__global__ __launch_bounds__(128) void ka_kernel() {
    extern __shared__ float sm[];
    float* Xs = sm;
    float* Ws = sm + 128*XPITCH;
    int rh = blockIdx.y;
    int r = rh >> 2, hh = rh & 3;
    int tile = blockIdx.x * 128;
    int tid = threadIdx.x;
    int ti = tid >> 3, tj = tid & 7;
    unsigned long long acc2[8][4];
    zero_acc(acc2);

#pragma unroll
    for (int p = 0; p < 16; p++) {
        int lr = p*8 + (tid >> 4);
        int lc = (tid & 15)*4;
        float4 x4 = make_float4(0.f, 0.f, 0.f, 0.f);
        int gi = tile + lr;
        if (gi < NNODES)
            x4 = *(const float4*)(g_k + (size_t)gi*DIM + hh*64 + lc);
        float* xp = Xs + lr*XPITCH + lc;
        xp[0] = x4.x; xp[1] = x4.y; xp[2] = x4.z; xp[3] = x4.w;
    }
    const float* src = g_At + (size_t)rh*DK*DK;  // contiguous 64x64 [e][d]
#pragma unroll
    for (int i = 0; i < 8; i++) {
        int lin = tid*32 + i*4;
        *(float4*)(Ws + lin) = *(const float4*)(src + lin);
    }
    __syncthreads();
    mm8x8(Xs, Ws, acc2, tid);
#pragma unroll
    for (int u = 0; u < 8; u++) {
        int gi = tile + ti*8 + u;
        if (gi < NNODES)
            store_row(g_kA + ((size_t)r*NNODES + gi)*DIM + hh*64 + tj*8, acc2[u]);
    }
}

// agg[c,h,:] = sum_r s[c,r,h,:] @ M[r,h]  : grid (157, 4), block 128
__global__ __launch_bounds__(128) void aggT_kernel(const float* __restrict__ rM) {
    extern __shared__ float sm[];
    float* Xs = sm;
    float* Ws = sm + 128*XPITCH;
    int hh = blockIdx.y;
    int tile = blockIdx.x * 128;
    int tid = threadIdx.x;
    int ti = tid >> 3, tj = tid & 7;
    unsigned long long acc2[8][4];
    zero_acc(acc2);

    for (int r = 0; r < NR; r++) {
        __syncthreads();
#pragma unroll
        for (int p = 0; p < 16; p++) {
            int lr = p*8 + (tid >> 4);
            int lc = (tid & 15)*4;
            float4 x4 = make_float4(0.f, 0.f, 0.f, 0.f);
            int gi = tile + lr;
            if (gi < NNODES)
                x4 = *(const float4*)(g_s + ((size_t)gi*NR + r)*DIM + hh*64 + lc);
            float* xp = Xs + lr*XPITCH + lc;
            xp[0] = x4.x; xp[1] = x4.y; xp[2] = x4.z; xp[3] = x4.w;
        }
        const float* src = rM + (size_t)(r*NH + hh)*DK*DK;  // M[r,h][d][j] row-major
#pragma unroll
        for (int i = 0; i < 8; i++) {
            int lin = tid*32 + i*4;
            *(float4*)(Ws + lin) = *(const float4*)(src + lin);
        }
        __syncthreads();
        mm8x8(Xs, Ws, acc2, tid);
    }
#pragma unroll
    for (int u = 0; u < 8; u++) {
        int gi = tile + ti*8 + u;
        if (gi < NNODES)
            store_row(g_agg + (size_t)gi*DIM + hh*64 + tj*8, acc2[u]);
    }
}

// out = sigmoid(skip[t]) * (agg @ a_linears[t]) : grid (157, type, coltile)
__global__ __launch_bounds__(128) void final_kernel(
    const float* __restrict__ aW, const float* __restrict__ skip, float* __restrict__ out) {
    extern __shared__ float sm[];
    float* Xs = sm;
    float* Ws = sm + 128*XPITCH;
    int t = blockIdx.y;
    int cnt = g_tcnt[t];
    int tile = blockIdx.x * 128;
    if (tile >= cnt) return;
    int base = g_toff[t];
    int c4 = blockIdx.z;
    const float* W = aW + (size_t)t*DIM*DIM + c4*64;
    int tid = threadIdx.x;
    int ti = tid >> 3, tj = tid & 7;
    unsigned long long acc2[8][4];
    zero_acc(acc2);

    for (int kb = 0; kb < 4; kb++) {
        __syncthreads();
#pragma unroll
        for (int p = 0; p < 16; p++) {
            int lr = p*8 + (tid >> 4);
            int lc = (tid & 15)*4;
            float4 x4 = make_float4(0.f, 0.f, 0.f, 0.f);
            int gi = tile + lr;
            if (gi < cnt) {
                int node = g_order[base + gi];
                x4 = *(const float4*)(g_agg + (size_t)node*DIM + kb*64 + lc);
            }
            float* xp = Xs + lr*XPITCH + lc;
            xp[0] = x4.x; xp[1] = x4.y; xp[2] = x4.z; xp[3] = x4.w;
        }
#pragma unroll
        for (int i = 0; i < 8; i++) {
            int lin = tid*32 + i*4;
            int kk = lin >> 6, d = lin & 63;
            float4 w4 = *(const float4*)(W + (size_t)(kb*64 + kk)*DIM + d);
            *(float4*)(Ws + kk*64 + d) = w4;
        }
        __syncthreads();
        mm8x8(Xs, Ws, acc2, tid);
    }
    float sig = 1.f / (1.f + __expf(-skip[t]));
    unsigned long long sig2 = pack2(sig, sig);
#pragma unroll
    for (int u = 0; u < 8; u++) {
        int gi = tile + ti*8 + u;
        if (gi < cnt) {
            int node = g_order[base + gi];
            unsigned long long row[4];
#pragma unroll
            for (int j = 0; j < 4; j++) row[j] = fmul2(acc2[u][j], sig2);
            store_row(out + (size_t)node*DIM + c4*64 + tj*8, row);
        }
    }
}

// ---------------- edge kernels ----------------
// one warp per edge, all 4 heads; lane 0 also counts the edge (fused ecount)
__global__ void score_kernel(const float* __restrict__ pri, const int* __restrict__ etype,
                             const int* __restrict__ rowi, const int* __restrict__ coli) {
    int gt = blockIdx.x*blockDim.x + threadIdx.x;
    int e = gt >> 5;
    int lane = gt & 31;
    if (e >= NEDGES) return;
    int r = etype[e];
    int row = rowi[e];
    int col = coli[e];
    if (lane == 0) atomicAdd(&g_cnt[col], 1);
    const float2* qp = (const float2*)(g_q + (size_t)col*DIM);
    const float2* kp = (const float2*)(g_kA + ((size_t)r*NNODES + row)*DIM);
#pragma unroll
    for (int hh = 0; hh < NH; hh++) {
        float2 qa = qp[hh*32 + lane];
        float2 ka = kp[hh*32 + lane];
        float s = qa.x*ka.x + qa.y*ka.y;
#pragma unroll
        for (int off = 16; off > 0; off >>= 1)
            s += __shfl_xor_sync(0xFFFFFFFFu, s, off);
        if (lane == 0) {
            float sc = s * pri[r*NH + hh] * 0.125f;   // 1/sqrt(64)
            g_ex[e*NH + hh] = sc;
            atomicMax(&g_mkey[col*NH + hh], fenc(sc));
        }
    }
}

__global__ void exden_kernel(const int* __restrict__ coli) {
    int i = blockIdx.x*blockDim.x + threadIdx.x;
    if (i >= NEDGES*NH) return;
    int e = i >> 2, hh = i & 3;
    int col = coli[e];
    float m = fdec(g_mkey[col*NH + hh]);
    float ex = __expf(g_ex[i] - m);
    g_ex[i] = ex;
    atomicAdd(&g_denom[col*NH + hh], ex);
}

// ---------------- CSR build ----------------
__global__ void csr_scan_kernel() {
    __shared__ int smv[1024];
    int T = threadIdx.x;
    int base = T * 20;
    int loc[20];
    int run = 0;
#pragma unroll
    for (int i = 0; i < 20; i++) {
        int idx = base + i;
        int c = (idx < NNODES) ? g_cnt[idx] : 0;
        loc[i] = run;
        run += c;
    }
    smv[T] = run;
    __syncthreads();
    for (int off = 1; off < 1024; off <<= 1) {
        int v = (T >= off) ? smv[T - off] : 0;
        __syncthreads();
        smv[T] += v;
        __syncthreads();
    }
    int excl = smv[T] - run;
#pragma unroll
    for (int i = 0; i < 20; i++) {
        int idx = base + i;
        if (idx < NNODES) {
            int v = excl + loc[i];
            g_rowptr[idx] = v;
            g_cursor[idx] = v;
        }
    }
    if (T == 1023) g_rowptr[NNODES] = smv[1023];
}

__global__ void escatter_kernel(const int* __restrict__ coli) {
    int e = blockIdx.x*blockDim.x + threadIdx.x;
    if (e < NEDGES) {
        int c = coli[e];
        int idx = atomicAdd(&g_cursor[c], 1);
        g_elist[idx] = e;
    }
}

// ---------------- per-destination aggregation ----------------
__global__ void aggregate_kernel(const int* __restrict__ etype, const int* __restrict__ rowi) {
    __shared__ float ss[NR*DIM];
    __shared__ float invd[NH];
    int c = blockIdx.x;
    int tid = threadIdx.x;
    int s0 = g_rowptr[c];
    int s1 = g_rowptr[c + 1];
#pragma unroll
    for (int r = 0; r < NR; r++) ss[r*DIM + tid] = 0.f;
    if (tid < NH) {
        float d = g_denom[c*NH + tid];
        invd[tid] = (d > 0.f) ? 1.f / d : 0.f;
    }
    __syncthreads();
    int hh = tid >> 6;
    for (int j = s0; j < s1; j++) {
        int e = g_elist[j];
        int r = etype[e];
        int row = rowi[e];
        float alpha = g_ex[e*NH + hh] * invd[hh];
        ss[r*DIM + tid] += alpha * g_v[(size_t)row*DIM + tid];
    }
#pragma unroll
    for (int r = 0; r < NR; r++)
        g_s[((size_t)c*NR + r)*DIM + tid] = ss[r*DIM + tid];
}

// ---------------- launch ----------------
extern "C" void kernel_launch(void* const* d_in, const int* in_sizes, int n_in,
                              void* d_out, int out_size) {
    const float* hin  = (const float*)d_in[0];
    const float* kW   = (const float*)d_in[1];
    const float* qW   = (const float*)d_in[2];
    const float* vW   = (const float*)d_in[3];
    const float* aW   = (const float*)d_in[4];
    const float* rA   = (const float*)d_in[5];
    const float* rM   = (const float*)d_in[6];
    const float* pri  = (const float*)d_in[7];
    const float* skip = (const float*)d_in[8];
    const int* ntype  = (const int*)d_in[9];
    const int* etype  = (const int*)d_in[10];
    const int* rowi   = (const int*)d_in[11];
    const int* coli   = (const int*)d_in[12];
    float* out = (float*)d_out;

    cudaFuncSetAttribute(kqv_kernel,   cudaFuncAttributeMaxDynamicSharedMemorySize, SMEM_BYTES);
    cudaFuncSetAttribute(ka_kernel,    cudaFuncAttributeMaxDynamicSharedMemorySize, SMEM_BYTES);
    cudaFuncSetAttribute(aggT_kernel,  cudaFuncAttributeMaxDynamicSharedMemorySize, SMEM_BYTES);
    cudaFuncSetAttribute(final_kernel, cudaFuncAttributeMaxDynamicSharedMemorySize, SMEM_BYTES);

    const int TILES = (NNODES + 127) / 128;  // 157

    // launch order arranged so #4 = kqv, #6 = ka (ncu capture window)
    zero_rest_kernel<<<(NNODES*NH + 255)/256, 256>>>();                 // 1
    combo_hist_kernel<<<1, 1024>>>(ntype);                              // 2
    nscatter_kernel<<<(NNODES + 255)/256, 256>>>(ntype);                // 3
    kqv_kernel<<<dim3(TILES, NT, 12), 128, SMEM_BYTES>>>(hin, kW, qW, vW); // 4
    trans_kernel<<<RH, 64>>>(rA);                                       // 5
    ka_kernel<<<dim3(TILES, RH), 128, SMEM_BYTES>>>();                  // 6
    score_kernel<<<(NEDGES*32 + 255)/256, 256>>>(pri, etype, rowi, coli);  // 7 (counts fused)
    exden_kernel<<<(NEDGES*NH + 255)/256, 256>>>(coli);                 // 8
    csr_scan_kernel<<<1, 1024>>>();                                     // 9
    escatter_kernel<<<(NEDGES + 255)/256, 256>>>(coli);                 // 10
    aggregate_kernel<<<NNODES, 256>>>(etype, rowi);                     // 11
    aggT_kernel<<<dim3(TILES, NH), 128, SMEM_BYTES>>>(rM);              // 12
    final_kernel<<<dim3(TILES, NT, NT), 128, SMEM_BYTES>>>(aW, skip, out); // 13
}

// round 12
// speedup vs baseline: 1.1269x; 1.1269x over previous
#include <cuda_runtime.h>
#include <math.h>

#define NNODES 20000
#define NEDGES 320000
#define NT 4
#define NR 8
#define NH 4
#define DK 64
#define DIM 256
#define RH (NR*NH)

#define XPITCH 68
// dynamic smem for GEMM kernels: Xs[128][68] + Ws[64][64]
#define SMEM_BYTES ((128*XPITCH + 64*64) * 4)

// ---------------- scratch (static device globals; no allocation) ----------------
__device__ float g_k[NNODES*DIM];
__device__ float g_q[NNODES*DIM];
__device__ float g_v[NNODES*DIM];
__device__ float g_agg[NNODES*DIM];
__device__ float g_At[RH*DK*DK];                    // transposed relation_att
__device__ float g_kA[(size_t)NR*NNODES*DIM];       // [R][N][H*64] = A_r,h @ k
__device__ float g_s[(size_t)NNODES*NR*DIM];        // [N][R][H*64] per-rel alpha-weighted v
__device__ float g_ex[NEDGES*NH];                   // scores, then exp values
__device__ unsigned int g_mkey[NNODES*NH];          // encoded float max keys
__device__ float g_denom[NNODES*NH];
__device__ int g_cnt[NNODES];
__device__ int g_rowptr[NNODES+1];
__device__ int g_cursor[NNODES];
__device__ int g_elist[NEDGES];
__device__ int g_tcnt[NT];
__device__ int g_toff[NT];
__device__ int g_tcur[NT];
__device__ int g_order[NNODES];

// ---------------- helpers ----------------
__device__ __forceinline__ unsigned fenc(float f) {
    unsigned u = __float_as_uint(f);
    return (u & 0x80000000u) ? ~u : (u | 0x80000000u);
}
__device__ __forceinline__ float fdec(unsigned k) {
    unsigned u = (k & 0x80000000u) ? (k & 0x7FFFFFFFu) : ~k;
    return __uint_as_float(u);
}

// ---- f32x2 packed math (sm_100+; ptxas never auto-generates FFMA2) ----
__device__ __forceinline__ unsigned long long pack2(float lo, float hi) {
    unsigned long long r;
    asm("mov.b64 %0, {%1, %2};" : "=l"(r) : "f"(lo), "f"(hi));
    return r;
}
__device__ __forceinline__ void ffma2(unsigned long long& d,
                                      unsigned long long a, unsigned long long b) {
    asm("fma.rn.f32x2 %0, %1, %2, %0;" : "+l"(d) : "l"(a), "l"(b));
}
__device__ __forceinline__ unsigned long long fmul2(unsigned long long a,
                                                    unsigned long long b) {
    unsigned long long r;
    asm("mul.rn.f32x2 %0, %1, %2;" : "=l"(r) : "l"(a), "l"(b));
    return r;
}
__device__ __forceinline__ float2 unpack2(unsigned long long v) {
    float2 f;
    asm("mov.b64 {%0, %1}, %2;" : "=f"(f.x), "=f"(f.y) : "l"(v));
    return f;
}

// 128x64 C-tile, 128 threads (4 warps), 8x8 microtile, K=64 step.
// Thread (warp w, ti4 = lane>>3, tj = lane&7) owns rows w*32 + u*4 + ti4
// (u = 0..7) and columns tj*8..tj*8+7.
// MIO-op minimization (the measured binder: l1tex__throughput 89.6%):
//  - a-side: one float4 LDS.128 per (u, 4-k block) = 2 ops/k/warp. For fixed u
//    the warp touches 4 addresses 272B apart (rows 1 apart, pitch 68*4B):
//    272 mod 128 = 16 -> distinct 16B banks -> 1 wavefront, broadcast over tj.
//  - w-side: 2 LDS.128 per k (data floor: 256B/k/warp).
//  => 4 MIO ops/k/warp vs 10 (R4) / 11 (R11 shuffle version).
// FFMA2 applied k-ascending: bit-identical numerics to all passing kernels.
__device__ __forceinline__ void mm8x8(const float* Xs, const float* Ws,
                                      unsigned long long acc2[8][4], int tid) {
    int lane = tid & 31;
    int tj = lane & 7;
    int ti4 = lane >> 3;                       // 0..3
    const float* abase = Xs + (size_t)((tid >> 5)*32 + ti4)*XPITCH;
#pragma unroll 4
    for (int k4 = 0; k4 < 16; k4++) {
        float4 a4[8];
#pragma unroll
        for (int u = 0; u < 8; u++)
            a4[u] = *(const float4*)(abase + u*4*XPITCH + k4*4);
#pragma unroll
        for (int kk = 0; kk < 4; kk++) {
            const float* w = Ws + (k4*4 + kk)*64 + tj*8;
            ulonglong2 wa = *(const ulonglong2*)w;
            ulonglong2 wb = *(const ulonglong2*)(w + 4);
#pragma unroll
            for (int u = 0; u < 8; u++) {
                float au = (kk == 0) ? a4[u].x : (kk == 1) ? a4[u].y
                         : (kk == 2) ? a4[u].z : a4[u].w;
                unsigned long long ad = pack2(au, au);
                ffma2(acc2[u][0], ad, wa.x);
                ffma2(acc2[u][1], ad, wa.y);
                ffma2(acc2[u][2], ad, wb.x);
                ffma2(acc2[u][3], ad, wb.y);
            }
        }
    }
}

__device__ __forceinline__ void zero_acc(unsigned long long acc2[8][4]) {
#pragma unroll
    for (int u = 0; u < 8; u++)
#pragma unroll
        for (int j = 0; j < 4; j++) acc2[u][j] = 0ULL;
}

__device__ __forceinline__ void store_row(float* cp, const unsigned long long* row) {
    float2 p0 = unpack2(row[0]), p1 = unpack2(row[1]);
    float2 p2 = unpack2(row[2]), p3 = unpack2(row[3]);
    *(float4*)cp       = make_float4(p0.x, p0.y, p1.x, p1.y);
    *(float4*)(cp + 4) = make_float4(p2.x, p2.y, p3.x, p3.y);
}

// row owned by this thread for accumulator index u (must match mm8x8)
__device__ __forceinline__ int owned_row(int tid, int u) {
    return (tid >> 5)*32 + u*4 + ((tid >> 3) & 3);
}

// ---------------- setup kernels ----------------
__global__ void zero_rest_kernel() {
    int i = blockIdx.x*blockDim.x + threadIdx.x;
    if (i < NNODES*NH) { g_mkey[i] = 0u; g_denom[i] = 0.f; }
    if (i < NNODES) g_cnt[i] = 0;
}

// self-contained type histogram + offsets + cursor reset (single block)
__global__ void combo_hist_kernel(const int* __restrict__ ntype) {
    __shared__ int scnt[NT];
    int tid = threadIdx.x;
    if (tid < NT) scnt[tid] = 0;
    __syncthreads();
    int c0 = 0, c1 = 0, c2 = 0, c3 = 0;
    for (int i = tid; i < NNODES; i += 1024) {
        int t = ntype[i];
        c0 += (t == 0); c1 += (t == 1); c2 += (t == 2); c3 += (t == 3);
    }
#pragma unroll
    for (int off = 16; off > 0; off >>= 1) {
        c0 += __shfl_xor_sync(0xFFFFFFFFu, c0, off);
        c1 += __shfl_xor_sync(0xFFFFFFFFu, c1, off);
        c2 += __shfl_xor_sync(0xFFFFFFFFu, c2, off);
        c3 += __shfl_xor_sync(0xFFFFFFFFu, c3, off);
    }
    if ((tid & 31) == 0) {
        atomicAdd(&scnt[0], c0); atomicAdd(&scnt[1], c1);
        atomicAdd(&scnt[2], c2); atomicAdd(&scnt[3], c3);
    }
    __syncthreads();
    if (tid == 0) {
        int off = 0;
        for (int t = 0; t < NT; t++) {
            g_tcnt[t] = scnt[t];
            g_toff[t] = off;
            g_tcur[t] = 0;
            off += scnt[t];
        }
    }
}

__global__ void nscatter_kernel(const int* __restrict__ ntype) {
    int n = blockIdx.x*blockDim.x + threadIdx.x;
    if (n < NNODES) {
        int t = ntype[n];
        int p = atomicAdd(&g_tcur[t], 1);
        g_order[g_toff[t] + p] = n;
    }
}

__global__ void trans_kernel(const float* __restrict__ rA) {
    int rh = blockIdx.x;        // 0..31
    int e = threadIdx.x;        // 0..63
    const float* src = rA + rh*DK*DK;
    float* dst = g_At + rh*DK*DK;
#pragma unroll
    for (int d = 0; d < DK; d++)
        dst[e*DK + d] = src[d*DK + e];   // At[e][d] = A[d][e]
}

// ---------------- GEMM kernels ----------------
// typed K/Q/V projection: grid (157, type, mat*4+coltile), block 128
__global__ __launch_bounds__(128) void kqv_kernel(
    const float* __restrict__ hin, const float* __restrict__ kW,
    const float* __restrict__ qW, const float* __restrict__ vW) {
    extern __shared__ float sm[];
    float* Xs = sm;                  // 128*XPITCH
    float* Ws = sm + 128*XPITCH;     // 64*64
    int t = blockIdx.y;
    int cnt = g_tcnt[t];
    int tile = blockIdx.x * 128;
    if (tile >= cnt) return;
    int base = g_toff[t];
    int mat = blockIdx.z >> 2;
    int c4  = blockIdx.z & 3;
    const float* W = (mat == 0 ? kW : (mat == 1 ? qW : vW)) + (size_t)t*DIM*DIM + c4*64;
    float* C = (mat == 0 ? g_k : (mat == 1 ? g_q : g_v));
    int tid = threadIdx.x;
    int tj = tid & 7;
    unsigned long long acc2[8][4];
    zero_acc(acc2);

    for (int kb = 0; kb < 4; kb++) {
        __syncthreads();
#pragma unroll
        for (int p = 0; p < 16; p++) {
            int lr = p*8 + (tid >> 4);
            int lc = (tid & 15)*4;
            float4 x4 = make_float4(0.f, 0.f, 0.f, 0.f);
            int gi = tile + lr;
            if (gi < cnt) {
                int node = g_order[base + gi];
                x4 = *(const float4*)(hin + (size_t)node*DIM + kb*64 + lc);
            }
            *(float4*)(Xs + lr*XPITCH + lc) = x4;
        }
#pragma unroll
        for (int i = 0; i < 8; i++) {
            int lin = tid*32 + i*4;
            int kk = lin >> 6, d = lin & 63;
            float4 w4 = *(const float4*)(W + (size_t)(kb*64 + kk)*DIM + d);
            *(float4*)(Ws + kk*64 + d) = w4;
        }
        __syncthreads();
        mm8x8(Xs, Ws, acc2, tid);
    }
#pragma unroll
    for (int u = 0; u < 8; u++) {
        int gi = tile + owned_row(tid, u);
        if (gi < cnt) {
            int node = g_order[base + gi];
            store_row(C + (size_t)node*DIM + c4*64 + tj*8, acc2[u]);
        }
    }
}

// kA[r,n,h,:] = A_{r,h} @ k[n,h,:]  : grid (157, 32), block 128
__global__ __launch_bounds__(128) void ka_kernel() {
    extern __shared__ float sm[];
    float* Xs = sm;
    float* Ws = sm + 128*XPITCH;
    int rh = blockIdx.y;
    int r = rh >> 2, hh = rh & 3;
    int tile = blockIdx.x * 128;
    int tid = threadIdx.x;
    int tj = tid & 7;
    unsigned long long acc2[8][4];
    zero_acc(acc2);

#pragma unroll
    for (int p = 0; p < 16; p++) {
        int lr = p*8 + (tid >> 4);
        int lc = (tid & 15)*4;
        float4 x4 = make_float4(0.f, 0.f, 0.f, 0.f);
        int gi = tile + lr;
        if (gi < NNODES)
            x4 = *(const float4*)(g_k + (size_t)gi*DIM + hh*64 + lc);
        *(float4*)(Xs + lr*XPITCH + lc) = x4;
    }
    const float* src = g_At + (size_t)rh*DK*DK;  // contiguous 64x64 [e][d]
#pragma unroll
    for (int i = 0; i < 8; i++) {
        int lin = tid*32 + i*4;
        *(float4*)(Ws + lin) = *(const float4*)(src + lin);
    }
    __syncthreads();
    mm8x8(Xs, Ws, acc2, tid);
#pragma unroll
    for (int u = 0; u < 8; u++) {
        int gi = tile + owned_row(tid, u);
        if (gi < NNODES)
            store_row(g_kA + ((size_t)r*NNODES + gi)*DIM + hh*64 + tj*8, acc2[u]);
    }
}

// agg[c,h,:] = sum_r s[c,r,h,:] @ M[r,h]  : grid (157, 4), block 128
__global__ __launch_bounds__(128) void aggT_kernel(const float* __restrict__ rM) {
    extern __shared__ float sm[];
    float* Xs = sm;
    float* Ws = sm + 128*XPITCH;
    int hh = blockIdx.y;
    int tile = blockIdx.x * 128;
    int tid = threadIdx.x;
    int tj = tid & 7;
    unsigned long long acc2[8][4];
    zero_acc(acc2);

    for (int r = 0; r < NR; r++) {
        __syncthreads();
#pragma unroll
        for (int p = 0; p < 16; p++) {
            int lr = p*8 + (tid >> 4);
            int lc = (tid & 15)*4;
            float4 x4 = make_float4(0.f, 0.f, 0.f, 0.f);
            int gi = tile + lr;
            if (gi < NNODES)
                x4 = *(const float4*)(g_s + ((size_t)gi*NR + r)*DIM + hh*64 + lc);
            *(float4*)(Xs + lr*XPITCH + lc) = x4;
        }
        const float* src = rM + (size_t)(r*NH + hh)*DK*DK;  // M[r,h][d][j] row-major
#pragma unroll
        for (int i = 0; i < 8; i++) {
            int lin = tid*32 + i*4;
            *(float4*)(Ws + lin) = *(const float4*)(src + lin);
        }
        __syncthreads();
        mm8x8(Xs, Ws, acc2, tid);
    }
#pragma unroll
    for (int u = 0; u < 8; u++) {
        int gi = tile + owned_row(tid, u);
        if (gi < NNODES)
            store_row(g_agg + (size_t)gi*DIM + hh*64 + tj*8, acc2[u]);
    }
}

// out = sigmoid(skip[t]) * (agg @ a_linears[t]) : grid (157, type, coltile)
__global__ __launch_bounds__(128) void final_kernel(
    const float* __restrict__ aW, const float* __restrict__ skip, float* __restrict__ out) {
    extern __shared__ float sm[];
    float* Xs = sm;
    float* Ws = sm + 128*XPITCH;
    int t = blockIdx.y;
    int cnt = g_tcnt[t];
    int tile = blockIdx.x * 128;
    if (tile >= cnt) return;
    int base = g_toff[t];
    int c4 = blockIdx.z;
    const float* W = aW + (size_t)t*DIM*DIM + c4*64;
    int tid = threadIdx.x;
    int tj = tid & 7;
    unsigned long long acc2[8][4];
    zero_acc(acc2);

    for (int kb = 0; kb < 4; kb++) {
        __syncthreads();
#pragma unroll
        for (int p = 0; p < 16; p++) {
            int lr = p*8 + (tid >> 4);
            int lc = (tid & 15)*4;
            float4 x4 = make_float4(0.f, 0.f, 0.f, 0.f);
            int gi = tile + lr;
            if (gi < cnt) {
                int node = g_order[base + gi];
                x4 = *(const float4*)(g_agg + (size_t)node*DIM + kb*64 + lc);
            }
            *(float4*)(Xs + lr*XPITCH + lc) = x4;
        }
#pragma unroll
        for (int i = 0; i < 8; i++) {
            int lin = tid*32 + i*4;
            int kk = lin >> 6, d = lin & 63;
            float4 w4 = *(const float4*)(W + (size_t)(kb*64 + kk)*DIM + d);
            *(float4*)(Ws + kk*64 + d) = w4;
        }
        __syncthreads();
        mm8x8(Xs, Ws, acc2, tid);
    }
    float sig = 1.f / (1.f + __expf(-skip[t]));
    unsigned long long sig2 = pack2(sig, sig);
#pragma unroll
    for (int u = 0; u < 8; u++) {
        int gi = tile + owned_row(tid, u);
        if (gi < cnt) {
            int node = g_order[base + gi];
            unsigned long long row[4];
#pragma unroll
            for (int j = 0; j < 4; j++) row[j] = fmul2(acc2[u][j], sig2);
            store_row(out + (size_t)node*DIM + c4*64 + tj*8, row);
        }
    }
}

// ---------------- edge kernels ----------------
// one warp per edge, all 4 heads; lane 0 also counts the edge (fused ecount)
__global__ void score_kernel(const float* __restrict__ pri, const int* __restrict__ etype,
                             const int* __restrict__ rowi, const int* __restrict__ coli) {
    int gt = blockIdx.x*blockDim.x + threadIdx.x;
    int e = gt >> 5;
    int lane = gt & 31;
    if (e >= NEDGES) return;
    int r = etype[e];
    int row = rowi[e];
    int col = coli[e];
    if (lane == 0) atomicAdd(&g_cnt[col], 1);
    const float2* qp = (const float2*)(g_q + (size_t)col*DIM);
    const float2* kp = (const float2*)(g_kA + ((size_t)r*NNODES + row)*DIM);
#pragma unroll
    for (int hh = 0; hh < NH; hh++) {
        float2 qa = qp[hh*32 + lane];
        float2 ka = kp[hh*32 + lane];
        float s = qa.x*ka.x + qa.y*ka.y;
#pragma unroll
        for (int off = 16; off > 0; off >>= 1)
            s += __shfl_xor_sync(0xFFFFFFFFu, s, off);
        if (lane == 0) {
            float sc = s * pri[r*NH + hh] * 0.125f;   // 1/sqrt(64)
            g_ex[e*NH + hh] = sc;
            atomicMax(&g_mkey[col*NH + hh], fenc(sc));
        }
    }
}

__global__ void exden_kernel(const int* __restrict__ coli) {
    int i = blockIdx.x*blockDim.x + threadIdx.x;
    if (i >= NEDGES*NH) return;
    int e = i >> 2, hh = i & 3;
    int col = coli[e];
    float m = fdec(g_mkey[col*NH + hh]);
    float ex = __expf(g_ex[i] - m);
    g_ex[i] = ex;
    atomicAdd(&g_denom[col*NH + hh], ex);
}

// ---------------- CSR build ----------------
__global__ void csr_scan_kernel() {
    __shared__ int smv[1024];
    int T = threadIdx.x;
    int base = T * 20;
    int loc[20];
    int run = 0;
#pragma unroll
    for (int i = 0; i < 20; i++) {
        int idx = base + i;
        int c = (idx < NNODES) ? g_cnt[idx] : 0;
        loc[i] = run;
        run += c;
    }
    smv[T] = run;
    __syncthreads();
    for (int off = 1; off < 1024; off <<= 1) {
        int v = (T >= off) ? smv[T - off] : 0;
        __syncthreads();
        smv[T] += v;
        __syncthreads();
    }
    int excl = smv[T] - run;
#pragma unroll
    for (int i = 0; i < 20; i++) {
        int idx = base + i;
        if (idx < NNODES) {
            int v = excl + loc[i];
            g_rowptr[idx] = v;
            g_cursor[idx] = v;
        }
    }
    if (T == 1023) g_rowptr[NNODES] = smv[1023];
}

__global__ void escatter_kernel(const int* __restrict__ coli) {
    int e = blockIdx.x*blockDim.x + threadIdx.x;
    if (e < NEDGES) {
        int c = coli[e];
        int idx = atomicAdd(&g_cursor[c], 1);
        g_elist[idx] = e;
    }
}

// ---------------- per-destination aggregation ----------------
__global__ void aggregate_kernel(const int* __restrict__ etype, const int* __restrict__ rowi) {
    __shared__ float ss[NR*DIM];
    __shared__ float invd[NH];
    int c = blockIdx.x;
    int tid = threadIdx.x;
    int s0 = g_rowptr[c];
    int s1 = g_rowptr[c + 1];
#pragma unroll
    for (int r = 0; r < NR; r++) ss[r*DIM + tid] = 0.f;
    if (tid < NH) {
        float d = g_denom[c*NH + tid];
        invd[tid] = (d > 0.f) ? 1.f / d : 0.f;
    }
    __syncthreads();
    int hh = tid >> 6;
    for (int j = s0; j < s1; j++) {
        int e = g_elist[j];
        int r = etype[e];
        int row = rowi[e];
        float alpha = g_ex[e*NH + hh] * invd[hh];
        ss[r*DIM + tid] += alpha * g_v[(size_t)row*DIM + tid];
    }
#pragma unroll
    for (int r = 0; r < NR; r++)
        g_s[((size_t)c*NR + r)*DIM + tid] = ss[r*DIM + tid];
}

// ---------------- launch ----------------
extern "C" void kernel_launch(void* const* d_in, const int* in_sizes, int n_in,
                              void* d_out, int out_size) {
    const float* hin  = (const float*)d_in[0];
    const float* kW   = (const float*)d_in[1];
    const float* qW   = (const float*)d_in[2];
    const float* vW   = (const float*)d_in[3];
    const float* aW   = (const float*)d_in[4];
    const float* rA   = (const float*)d_in[5];
    const float* rM   = (const float*)d_in[6];
    const float* pri  = (const float*)d_in[7];
    const float* skip = (const float*)d_in[8];
    const int* ntype  = (const int*)d_in[9];
    const int* etype  = (const int*)d_in[10];
    const int* rowi   = (const int*)d_in[11];
    const int* coli   = (const int*)d_in[12];
    float* out = (float*)d_out;

    cudaFuncSetAttribute(kqv_kernel,   cudaFuncAttributeMaxDynamicSharedMemorySize, SMEM_BYTES);
    cudaFuncSetAttribute(ka_kernel,    cudaFuncAttributeMaxDynamicSharedMemorySize, SMEM_BYTES);
    cudaFuncSetAttribute(aggT_kernel,  cudaFuncAttributeMaxDynamicSharedMemorySize, SMEM_BYTES);
    cudaFuncSetAttribute(final_kernel, cudaFuncAttributeMaxDynamicSharedMemorySize, SMEM_BYTES);

    const int TILES = (NNODES + 127) / 128;  // 157

    // launch order arranged so #4 = kqv, #6 = ka (ncu capture window)
    zero_rest_kernel<<<(NNODES*NH + 255)/256, 256>>>();                 // 1
    combo_hist_kernel<<<1, 1024>>>(ntype);                              // 2
    nscatter_kernel<<<(NNODES + 255)/256, 256>>>(ntype);                // 3
    kqv_kernel<<<dim3(TILES, NT, 12), 128, SMEM_BYTES>>>(hin, kW, qW, vW); // 4
    trans_kernel<<<RH, 64>>>(rA);                                       // 5
    ka_kernel<<<dim3(TILES, RH), 128, SMEM_BYTES>>>();                  // 6
    score_kernel<<<(NEDGES*32 + 255)/256, 256>>>(pri, etype, rowi, coli);  // 7 (counts fused)
    exden_kernel<<<(NEDGES*NH + 255)/256, 256>>>(coli);                 // 8
    csr_scan_kernel<<<1, 1024>>>();                                     // 9
    escatter_kernel<<<(NEDGES + 255)/256, 256>>>(coli);                 // 10
    aggregate_kernel<<<NNODES, 256>>>(etype, rowi);                     // 11
    aggT_kernel<<<dim3(TILES, NH), 128, SMEM_BYTES>>>(rM);              // 12
    final_kernel<<<dim3(TILES, NT, NT), 128, SMEM_BYTES>>>(aW, skip, out); // 13
}